// round 2
// baseline (speedup 1.0000x reference)
#include <cuda_runtime.h>
#include <math.h>

// Problem shape (fixed for this problem instance)
#define D_IN   1024
#define HDIM   1024
#define BMAX   64
#define TMAXQ  1000
#define NGATE  4096   // 4*HDIM

#define TOTAL_MAX 47872
#define NBLK   128     // persistent blocks (<= 148 SMs, 1 per SM)

// ---------------- device scratch (no allocations allowed) ----------------
__device__ float g_gates[(size_t)TOTAL_MAX * NGATE];   // ~784 MB: x@W_ih^T + bias
__device__ float g_hA[BMAX * HDIM];
__device__ float g_hB[BMAX * HDIM];
__device__ float g_cS[BMAX * HDIM];
__device__ int   g_bs[TMAXQ];
__device__ int   g_off[TMAXQ + 1];
__device__ unsigned g_bar;

// ---------------- prep: decode batch_sizes (int32 OR int64), prefix sum, init ----
__global__ void prep_kernel(const void* __restrict__ bs_raw,
                            const float* __restrict__ h0,
                            const float* __restrict__ c0,
                            int T) {
    __shared__ int sbs[TMAXQ];
    const int* p = (const int*)bs_raw;
    // int64 little-endian: high word of element 0 is 0; int32: element 1 >= 1
    bool is64 = (p[1] == 0);
    int tid = threadIdx.x;
    for (int t = tid; t < T; t += blockDim.x)
        sbs[t] = is64 ? p[2 * t] : p[t];
    __syncthreads();
    if (tid == 0) {
        g_bar = 0u;                       // reset persistent-kernel barrier
        int acc = 0;
        for (int t = 0; t < T; t++) {
            g_off[t] = acc;
            g_bs[t] = sbs[t];
            acc += sbs[t];
        }
        g_off[T] = acc;
    }
    for (int i = tid; i < BMAX * HDIM; i += blockDim.x) {
        g_hA[i] = h0[i];
        g_cS[i] = c0[i];
    }
}

// ---------------- input GEMM: G = data @ W_ih^T + (b_ih + b_hh) ----------------
// Tiles: BM=128, BN=64, BK=16; 256 threads; 8x4 per thread; fp32.
__global__ __launch_bounds__(256) void gemm_input(
    const float* __restrict__ data,   // [total, 1024]
    const float* __restrict__ W,      // [4096, 1024]
    const float* __restrict__ b_ih,
    const float* __restrict__ b_hh,
    int total) {
    __shared__ __align__(16) float As[16][128];
    __shared__ __align__(16) float Bs[16][64];

    int tid = threadIdx.x;
    int tx = tid & 15;        // col group (4 cols)
    int ty = tid >> 4;        // row group (8 rows)
    int row0 = blockIdx.x * 128;
    int col0 = blockIdx.y * 64;

    float acc[8][4];
#pragma unroll
    for (int i = 0; i < 8; i++)
#pragma unroll
        for (int j = 0; j < 4; j++) acc[i][j] = 0.f;

    int bm = tid >> 2;             // 0..63 (B tile row)
    int bkq = (tid & 3) * 4;

    for (int kt = 0; kt < D_IN; kt += 16) {
#pragma unroll
        for (int r = 0; r < 2; r++) {
            int chunk = tid + r * 256;
            int m = chunk >> 2;
            int kq = (chunk & 3) * 4;
            int row = row0 + m;
            if (row >= total) row = total - 1;
            float4 v = *(const float4*)&data[(size_t)row * D_IN + kt + kq];
            As[kq + 0][m] = v.x; As[kq + 1][m] = v.y;
            As[kq + 2][m] = v.z; As[kq + 3][m] = v.w;
        }
        {
            float4 v = *(const float4*)&W[(size_t)(col0 + bm) * D_IN + kt + bkq];
            Bs[bkq + 0][bm] = v.x; Bs[bkq + 1][bm] = v.y;
            Bs[bkq + 2][bm] = v.z; Bs[bkq + 3][bm] = v.w;
        }
        __syncthreads();
#pragma unroll
        for (int k = 0; k < 16; k++) {
            float4 a0 = *(const float4*)&As[k][ty * 8];
            float4 a1 = *(const float4*)&As[k][ty * 8 + 4];
            float4 b  = *(const float4*)&Bs[k][tx * 4];
            acc[0][0] += a0.x * b.x; acc[0][1] += a0.x * b.y; acc[0][2] += a0.x * b.z; acc[0][3] += a0.x * b.w;
            acc[1][0] += a0.y * b.x; acc[1][1] += a0.y * b.y; acc[1][2] += a0.y * b.z; acc[1][3] += a0.y * b.w;
            acc[2][0] += a0.z * b.x; acc[2][1] += a0.z * b.y; acc[2][2] += a0.z * b.z; acc[2][3] += a0.z * b.w;
            acc[3][0] += a0.w * b.x; acc[3][1] += a0.w * b.y; acc[3][2] += a0.w * b.z; acc[3][3] += a0.w * b.w;
            acc[4][0] += a1.x * b.x; acc[4][1] += a1.x * b.y; acc[4][2] += a1.x * b.z; acc[4][3] += a1.x * b.w;
            acc[5][0] += a1.y * b.x; acc[5][1] += a1.y * b.y; acc[5][2] += a1.y * b.z; acc[5][3] += a1.y * b.w;
            acc[6][0] += a1.z * b.x; acc[6][1] += a1.z * b.y; acc[6][2] += a1.z * b.z; acc[6][3] += a1.z * b.w;
            acc[7][0] += a1.w * b.x; acc[7][1] += a1.w * b.y; acc[7][2] += a1.w * b.z; acc[7][3] += a1.w * b.w;
        }
        __syncthreads();
    }

#pragma unroll
    for (int j = 0; j < 4; j++) {
        int n = col0 + tx * 4 + j;
        float bias = b_ih[n] + b_hh[n];
#pragma unroll
        for (int i = 0; i < 8; i++) {
            int row = row0 + ty * 8 + i;
            if (row < total)
                g_gates[(size_t)row * NGATE + n] = acc[i][j] + bias;
        }
    }
}

// ---------------- persistent recurrent kernel -------------------------------
// 128 blocks x 128 threads, 1 block/SM, all co-resident. Block owns 8 hidden
// units (32 gate cols). W_hh slice (32 cols x 1024 k = 128KB) cached in smem
// ONCE. Per step: h tile staged per ktile, 4x4 fp32 accum, fused pointwise,
// software grid barrier between steps. h reads use __ldcg (cross-SM coherence).
#define KT 32
// dynamic smem layout (floats): sW[32*1024] | Hs[KT*64] | Gs[64*32]
#define SMEM_FLOATS (32 * 1024 + KT * 64 + 64 * 32)

__global__ __launch_bounds__(128) void step_persistent(
    const float* __restrict__ W_hh,   // [4096, 1024]
    float* __restrict__ out,          // packed output [total, 1024]
    int T) {
    extern __shared__ __align__(16) float smem[];
    float* sW = smem;                    // [k*32 + c]
    float* Hs = smem + 32 * 1024;        // [kl*64 + b]
    float* Gs = Hs + KT * 64;            // [b*32 + c]

    int tid = threadIdx.x;
    int j0 = blockIdx.x * 8;

    // one-time: cache this block's W_hh slice in smem (32 cols x 1024 k)
    for (int i = tid; i < 32 * 256; i += 128) {
        int c = i >> 8;                 // 0..31
        int kq = (i & 255) * 4;
        int n = (c >> 3) * HDIM + j0 + (c & 7);
        float4 v = *(const float4*)&W_hh[(size_t)n * HDIM + kq];
        sW[(kq + 0) * 32 + c] = v.x; sW[(kq + 1) * 32 + c] = v.y;
        sW[(kq + 2) * 32 + c] = v.z; sW[(kq + 3) * 32 + c] = v.w;
    }
    __syncthreads();

    int cx = tid & 7;      // col group (4 cols)
    int ry = tid >> 3;     // row group (4 rows), 0..15

    for (int t = 0; t < T; t++) {
        const float* hprev = (t & 1) ? g_hB : g_hA;
        float* hnext       = (t & 1) ? g_hA : g_hB;
        int Bt  = g_bs[t];
        int off = g_off[t];
        bool active = (ry * 4) < Bt;

        float acc[4][4];
#pragma unroll
        for (int i = 0; i < 4; i++)
#pragma unroll
            for (int j = 0; j < 4; j++) acc[i][j] = 0.f;

        for (int kt = 0; kt < HDIM; kt += KT) {
            // stage h tile: 64 rows x 32 k (bypass L1: written by other SMs)
#pragma unroll
            for (int r = 0; r < 4; r++) {
                int chunk = tid + r * 128;
                int b  = chunk >> 3;
                int kq = (chunk & 7) * 4;
                float4 v = __ldcg((const float4*)&hprev[(size_t)b * HDIM + kt + kq]);
                Hs[(kq + 0) * 64 + b] = v.x; Hs[(kq + 1) * 64 + b] = v.y;
                Hs[(kq + 2) * 64 + b] = v.z; Hs[(kq + 3) * 64 + b] = v.w;
            }
            __syncthreads();
            if (active) {
#pragma unroll
                for (int k = 0; k < KT; k++) {
                    float4 a = *(const float4*)&Hs[k * 64 + ry * 4];
                    float4 b = *(const float4*)&sW[(kt + k) * 32 + cx * 4];
                    acc[0][0] += a.x * b.x; acc[0][1] += a.x * b.y; acc[0][2] += a.x * b.z; acc[0][3] += a.x * b.w;
                    acc[1][0] += a.y * b.x; acc[1][1] += a.y * b.y; acc[1][2] += a.y * b.z; acc[1][3] += a.y * b.w;
                    acc[2][0] += a.z * b.x; acc[2][1] += a.z * b.y; acc[2][2] += a.z * b.z; acc[2][3] += a.z * b.w;
                    acc[3][0] += a.w * b.x; acc[3][1] += a.w * b.y; acc[3][2] += a.w * b.z; acc[3][3] += a.w * b.w;
                }
            }
            __syncthreads();
        }

        // stash recurrent gate contributions
        if (active) {
#pragma unroll
            for (int i = 0; i < 4; i++)
#pragma unroll
                for (int j = 0; j < 4; j++)
                    Gs[(ry * 4 + i) * 32 + cx * 4 + j] = acc[i][j];
        }
        __syncthreads();

        // pointwise LSTM update; frozen rows propagate to hnext
        for (int it = tid; it < 64 * 8; it += 128) {
            int b  = it >> 3;
            int jl = it & 7;
            int j  = j0 + jl;
            if (b < Bt) {
                size_t gro = (size_t)(off + b) * NGATE;
                float gi = Gs[b * 32 + 0  + jl] + g_gates[gro + 0 * HDIM + j];
                float gf = Gs[b * 32 + 8  + jl] + g_gates[gro + 1 * HDIM + j];
                float gg = Gs[b * 32 + 16 + jl] + g_gates[gro + 2 * HDIM + j];
                float go = Gs[b * 32 + 24 + jl] + g_gates[gro + 3 * HDIM + j];
                float i_ = 1.f / (1.f + __expf(-gi));
                float f_ = 1.f / (1.f + __expf(-gf));
                float g_ = tanhf(gg);
                float o_ = 1.f / (1.f + __expf(-go));
                float c_old = g_cS[b * HDIM + j];
                float c2 = f_ * c_old + i_ * g_;
                float h2 = o_ * tanhf(c2);
                g_cS[b * HDIM + j] = c2;
                hnext[b * HDIM + j] = h2;
                out[(size_t)(off + b) * HDIM + j] = h2;
            } else {
                hnext[b * HDIM + j] = __ldcg(&hprev[b * HDIM + j]);
            }
        }

        // ---- software grid barrier (all blocks co-resident) ----
        __syncthreads();
        if (tid == 0) {
            __threadfence();
            atomicAdd(&g_bar, 1u);
            unsigned target = (unsigned)(t + 1) * (unsigned)NBLK;
            while (*(volatile unsigned*)&g_bar < target) { }
            __threadfence();
        }
        __syncthreads();
    }
}

// ---------------- final: h_f, c_f -> tail of d_out ----------------
__global__ void final_kernel(float* __restrict__ out, int total, int finalA) {
    const float* hf = finalA ? g_hA : g_hB;
    size_t base = (size_t)total * HDIM;
    int n = BMAX * HDIM;
    for (int i = blockIdx.x * blockDim.x + threadIdx.x; i < n;
         i += gridDim.x * blockDim.x) {
        out[base + i]     = hf[i];
        out[base + n + i] = g_cS[i];
    }
}

// ---------------- launch ----------------
extern "C" void kernel_launch(void* const* d_in, const int* in_sizes, int n_in,
                              void* d_out, int out_size) {
    const float* data = (const float*)d_in[0];
    const void*  bs   = d_in[1];
    const float* W_ih = (const float*)d_in[2];
    const float* W_hh = (const float*)d_in[3];
    const float* b_ih = (const float*)d_in[4];
    const float* b_hh = (const float*)d_in[5];
    const float* h0   = (const float*)d_in[6];
    const float* c0   = (const float*)d_in[7];
    float* out = (float*)d_out;

    int total = in_sizes[0] / D_IN;
    int T = in_sizes[1];
    if (T > TMAXQ) T = T / 2;   // int64 batch_sizes reported as int32-pair count
    if (T > TMAXQ) T = TMAXQ;

    cudaFuncSetAttribute(step_persistent,
                         cudaFuncAttributeMaxDynamicSharedMemorySize,
                         SMEM_FLOATS * (int)sizeof(float));

    prep_kernel<<<1, 256>>>(bs, h0, c0, T);

    dim3 grid((total + 127) / 128, NGATE / 64);
    gemm_input<<<grid, 256>>>(data, W_ih, b_ih, b_hh, total);

    step_persistent<<<NBLK, 128, SMEM_FLOATS * (int)sizeof(float)>>>(W_hh, out, T);

    long long need = (long long)total * HDIM + 2LL * BMAX * HDIM;
    if ((long long)out_size >= need)
        final_kernel<<<64, 256>>>(out, total, (T & 1) ? 0 : 1);
}

// round 5
// speedup vs baseline: 2.7445x; 2.7445x over previous
#include <cuda_runtime.h>
#include <cuda_bf16.h>
#include <math.h>
#include <stdint.h>

#define D_IN   1024
#define HDIM   1024
#define BMAX   64
#define TMAXQ  1000
#define NGATE  4096
#define TOTAL_MAX 47872
#define NBLK   128

// ---------------- device scratch ----------------
__device__ float g_gates[(size_t)TOTAL_MAX * NGATE];           // ~784MB
__device__ __nv_bfloat16 g_data_hi[(size_t)TOTAL_MAX * D_IN];
__device__ __nv_bfloat16 g_data_lo[(size_t)TOTAL_MAX * D_IN];
__device__ __nv_bfloat16 g_w_hi[(size_t)NGATE * D_IN];
__device__ __nv_bfloat16 g_w_lo[(size_t)NGATE * D_IN];
__device__ __nv_bfloat16 g_h16hi[2][BMAX * HDIM];
__device__ __nv_bfloat16 g_h16lo[2][BMAX * HDIM];
__device__ float g_hA[BMAX * HDIM];
__device__ float g_hB[BMAX * HDIM];
__device__ float g_cS[BMAX * HDIM];
__device__ int   g_bs[TMAXQ];
__device__ int   g_off[TMAXQ + 1];
__device__ unsigned g_bar;

// ---------------- helpers ----------------
__device__ __forceinline__ uint32_t smem_u32(const void* p) {
    uint32_t a;
    asm("{ .reg .u64 t; cvta.to.shared.u64 t, %1; cvt.u32.u64 %0, t; }" : "=r"(a) : "l"(p));
    return a;
}
__device__ __forceinline__ void cp16(uint32_t dst, const void* src) {
    asm volatile("cp.async.cg.shared.global [%0], [%1], 16;" :: "r"(dst), "l"(src));
}
#define CP_COMMIT() asm volatile("cp.async.commit_group;" ::: "memory")
#define CP_WAIT1()  asm volatile("cp.async.wait_group 1;"  ::: "memory")
#define CP_WAIT0()  asm volatile("cp.async.wait_group 0;"  ::: "memory")

__device__ __forceinline__ void mma16816(float& d0, float& d1, float& d2, float& d3,
                                         uint32_t a0, uint32_t a1, uint32_t a2, uint32_t a3,
                                         uint32_t b0, uint32_t b1) {
    asm volatile(
        "mma.sync.aligned.m16n8k16.row.col.f32.bf16.bf16.f32 "
        "{%0,%1,%2,%3}, {%4,%5,%6,%7}, {%8,%9}, {%0,%1,%2,%3};"
        : "+f"(d0), "+f"(d1), "+f"(d2), "+f"(d3)
        : "r"(a0), "r"(a1), "r"(a2), "r"(a3), "r"(b0), "r"(b1));
}

__device__ __forceinline__ uint32_t pack_bf16(__nv_bfloat16 lo, __nv_bfloat16 hi) {
    return (uint32_t)__bfloat16_as_ushort(lo) | ((uint32_t)__bfloat16_as_ushort(hi) << 16);
}

// ---------------- prep ----------------
__global__ void prep_kernel(const void* __restrict__ bs_raw,
                            const float* __restrict__ h0,
                            const float* __restrict__ c0, int T) {
    __shared__ int sbs[TMAXQ];
    const int* p = (const int*)bs_raw;
    bool is64 = (p[1] == 0);
    int tid = threadIdx.x;
    for (int t = tid; t < T; t += blockDim.x) sbs[t] = is64 ? p[2 * t] : p[t];
    __syncthreads();
    if (tid == 0) {
        g_bar = 0u;
        int acc = 0;
        for (int t = 0; t < T; t++) { g_off[t] = acc; g_bs[t] = sbs[t]; acc += sbs[t]; }
        g_off[T] = acc;
    }
    for (int i = tid; i < BMAX * HDIM; i += blockDim.x) {
        float x = h0[i];
        g_hA[i] = x;
        g_cS[i] = c0[i];
        __nv_bfloat16 hh = __float2bfloat16(x);
        g_h16hi[0][i] = hh;
        g_h16lo[0][i] = __float2bfloat16(x - __bfloat162float(hh));
    }
}

// ---------------- fp32 -> bf16 hi/lo split ----------------
__global__ void split_kernel(const float* __restrict__ src,
                             __nv_bfloat16* __restrict__ hi,
                             __nv_bfloat16* __restrict__ lo, size_t n) {
    for (size_t i = (size_t)blockIdx.x * blockDim.x + threadIdx.x; i < n;
         i += (size_t)gridDim.x * blockDim.x) {
        float x = src[i];
        __nv_bfloat16 h = __float2bfloat16(x);
        hi[i] = h;
        lo[i] = __float2bfloat16(x - __bfloat162float(h));
    }
}

// ---------------- input GEMM via mma.sync bf16 split -------------------------
// BM=128, BN=128, BK=32; keff = 3072 (A:[hi,hi,lo], B:[hi,lo,hi]); 8 warps.
#define GI_STR    80
#define GI_OFF_BIAS 0
#define GI_OFF_A  512
#define GI_STG    (128 * GI_STR)
#define GI_OFF_B  (GI_OFF_A + 2 * GI_STG)
#define GI_SMEM   (GI_OFF_B + 2 * GI_STG)

__global__ __launch_bounds__(256) void gemm_input_tc(
    const float* __restrict__ b_ih, const float* __restrict__ b_hh, int total) {
    extern __shared__ __align__(16) char sm[];
    float* sBias = (float*)(sm + GI_OFF_BIAS);
    uint32_t sb = smem_u32(sm);
    int tid = threadIdx.x, wid = tid >> 5, lane = tid & 31;
    int g = lane >> 2, tq = lane & 3;
    int row0 = blockIdx.x * 128, col0 = blockIdx.y * 128;
    int wm = wid & 1, wn = wid >> 1;

    for (int i = tid; i < 128; i += 256) sBias[i] = b_ih[col0 + i] + b_hh[col0 + i];

    float acc[4][4][4];
#pragma unroll
    for (int mf = 0; mf < 4; mf++)
#pragma unroll
        for (int nf = 0; nf < 4; nf++)
#pragma unroll
            for (int q = 0; q < 4; q++) acc[mf][nf][q] = 0.f;

    auto do_stage = [&](int st) {
        int buf = st & 1;
        int keff = st * 32;
        int s = keff >> 10, k0 = keff & 1023;
        const __nv_bfloat16* As = (s == 2) ? g_data_lo : g_data_hi;
        const __nv_bfloat16* Bs = (s == 1) ? g_w_lo : g_w_hi;
#pragma unroll
        for (int r = 0; r < 2; r++) {
            int c = tid + r * 256;
            int m = c >> 2, kc = (c & 3) * 8;
            int row = row0 + m; if (row >= total) row = total - 1;
            cp16(sb + GI_OFF_A + buf * GI_STG + m * GI_STR + kc * 2,
                 As + (size_t)row * 1024 + k0 + kc);
        }
#pragma unroll
        for (int r = 0; r < 2; r++) {
            int c = tid + r * 256;
            int m = c >> 2, kc = (c & 3) * 8;
            cp16(sb + GI_OFF_B + buf * GI_STG + m * GI_STR + kc * 2,
                 Bs + (size_t)(col0 + m) * 1024 + k0 + kc);
        }
        CP_COMMIT();
    };

    do_stage(0);
    for (int st = 0; st < 96; ++st) {
        if (st < 95) { do_stage(st + 1); CP_WAIT1(); } else { CP_WAIT0(); }
        __syncthreads();
        int buf = st & 1;
        const char* pA = sm + GI_OFF_A + buf * GI_STG;
        const char* pB = sm + GI_OFF_B + buf * GI_STG;
#pragma unroll
        for (int kk = 0; kk < 32; kk += 16) {
            uint32_t aF[4][4], bF[4][2];
#pragma unroll
            for (int mf = 0; mf < 4; mf++) {
                const char* p = pA + (wm * 64 + mf * 16 + g) * GI_STR + (kk + tq * 2) * 2;
                aF[mf][0] = *(const uint32_t*)p;
                aF[mf][1] = *(const uint32_t*)(p + 8 * GI_STR);
                aF[mf][2] = *(const uint32_t*)(p + 16);
                aF[mf][3] = *(const uint32_t*)(p + 8 * GI_STR + 16);
            }
#pragma unroll
            for (int nf = 0; nf < 4; nf++) {
                const char* p = pB + (wn * 32 + nf * 8 + g) * GI_STR + (kk + tq * 2) * 2;
                bF[nf][0] = *(const uint32_t*)p;
                bF[nf][1] = *(const uint32_t*)(p + 16);
            }
#pragma unroll
            for (int mf = 0; mf < 4; mf++)
#pragma unroll
                for (int nf = 0; nf < 4; nf++)
                    mma16816(acc[mf][nf][0], acc[mf][nf][1], acc[mf][nf][2], acc[mf][nf][3],
                             aF[mf][0], aF[mf][1], aF[mf][2], aF[mf][3],
                             bF[nf][0], bF[nf][1]);
        }
        __syncthreads();
    }

#pragma unroll
    for (int mf = 0; mf < 4; mf++) {
        int r0 = row0 + wm * 64 + mf * 16 + g;
#pragma unroll
        for (int nf = 0; nf < 4; nf++) {
            int cl = wn * 32 + nf * 8 + tq * 2;
            float bb0 = sBias[cl], bb1 = sBias[cl + 1];
            if (r0 < total) {
                float2 v = { acc[mf][nf][0] + bb0, acc[mf][nf][1] + bb1 };
                *(float2*)&g_gates[(size_t)r0 * NGATE + col0 + cl] = v;
            }
            if (r0 + 8 < total) {
                float2 v = { acc[mf][nf][2] + bb0, acc[mf][nf][3] + bb1 };
                *(float2*)&g_gates[(size_t)(r0 + 8) * NGATE + col0 + cl] = v;
            }
        }
    }
}

// ---------------- persistent recurrence via mma.sync -------------------------
#define RW_STR   2064
#define R_WSEG   (32 * RW_STR)
#define R_OFF_A  (2 * R_WSEG)
#define RA_STR   272
#define R_ASTG   (64 * RA_STR)
#define R_OFF_GS (R_OFF_A + 2 * R_ASTG)
#define R_OFF_SG (R_OFF_GS + 4 * 8192)
#define R_SMEM   (R_OFF_SG + 8192)

__global__ __launch_bounds__(256) void step_persistent(
    const float* __restrict__ W_hh, float* __restrict__ out, int T) {
    extern __shared__ __align__(16) char sm[];
    uint32_t sb = smem_u32(sm);
    float* GsAll = (float*)(sm + R_OFF_GS);
    float* sG = (float*)(sm + R_OFF_SG);
    int tid = threadIdx.x, wid = tid >> 5, lane = tid & 31;
    int g = lane >> 2, tq = lane & 3;
    int j0 = blockIdx.x * 8;
    int mw = wid & 1, kteam = wid >> 1;

    // one-time: convert this block's W_hh cols (fp32 -> bf16 hi/lo)
    for (int idx = tid; idx < 8192; idx += 256) {
        int c = idx >> 8;
        int k = (idx & 255) * 4;
        int n = (c >> 3) * HDIM + j0 + (c & 7);
        float4 v = *(const float4*)&W_hh[(size_t)n * HDIM + k];
        __nv_bfloat16 h0 = __float2bfloat16(v.x), h1 = __float2bfloat16(v.y);
        __nv_bfloat16 h2 = __float2bfloat16(v.z), h3 = __float2bfloat16(v.w);
        __nv_bfloat16 l0 = __float2bfloat16(v.x - __bfloat162float(h0));
        __nv_bfloat16 l1 = __float2bfloat16(v.y - __bfloat162float(h1));
        __nv_bfloat16 l2 = __float2bfloat16(v.z - __bfloat162float(h2));
        __nv_bfloat16 l3 = __float2bfloat16(v.w - __bfloat162float(h3));
        char* ph = sm + c * RW_STR + k * 2;
        char* pl = ph + R_WSEG;
        *(uint32_t*)ph = pack_bf16(h0, h1); *(uint32_t*)(ph + 4) = pack_bf16(h2, h3);
        *(uint32_t*)pl = pack_bf16(l0, l1); *(uint32_t*)(pl + 4) = pack_bf16(l2, l3);
    }
    __syncthreads();

    for (int t = 0; t < T; t++) {
        int pr = t & 1;
        const __nv_bfloat16* hhi = g_h16hi[pr];
        const __nv_bfloat16* hlo = g_h16lo[pr];
        int Bt = g_bs[t], off = g_off[t];

        auto stageA = [&](int st) {
            int buf = st & 1;
            const __nv_bfloat16* src = (st < 8) ? hhi : hlo;
            int k0 = (st & 7) * 128;
#pragma unroll
            for (int r = 0; r < 4; r++) {
                int c = tid + r * 256;
                int b = c >> 4, kc = (c & 15) * 8;
                cp16(sb + R_OFF_A + buf * R_ASTG + b * RA_STR + kc * 2,
                     src + b * 1024 + k0 + kc);
            }
        };

        {
#pragma unroll
            for (int u = 0; u < 2; u++) {
                int id = tid * 2 + u;
                int b = id >> 3, gi = (id >> 1) & 3, half = id & 1;
                int bc = (b < Bt) ? b : (Bt - 1);
                cp16(sb + R_OFF_SG + (uint32_t)(b * 32 + gi * 8 + half * 4) * 4,
                     &g_gates[(size_t)(off + bc) * NGATE + gi * HDIM + j0 + half * 4]);
            }
            stageA(0);
            CP_COMMIT();
        }

        float acc[2][4][4];
#pragma unroll
        for (int mf = 0; mf < 2; mf++)
#pragma unroll
            for (int nf = 0; nf < 4; nf++)
#pragma unroll
                for (int q = 0; q < 4; q++) acc[mf][nf][q] = 0.f;

        for (int st = 0; st < 16; ++st) {
            if (st < 15) { stageA(st + 1); CP_COMMIT(); CP_WAIT1(); } else { CP_WAIT0(); }
            __syncthreads();
            int buf = st & 1;
            const char* pA = sm + R_OFF_A + buf * R_ASTG;
            bool two = (st < 8);
            int k0w = (st & 7) * 128;              // FIX: global k offset into W smem
#pragma unroll
            for (int u = 0; u < 2; u++) {
                int kk = (kteam * 2 + u) * 16;
                uint32_t aF[2][4], bH[4][2];
#pragma unroll
                for (int mf = 0; mf < 2; mf++) {
                    const char* p = pA + (mw * 32 + mf * 16 + g) * RA_STR + (kk + tq * 2) * 2;
                    aF[mf][0] = *(const uint32_t*)p;
                    aF[mf][1] = *(const uint32_t*)(p + 8 * RA_STR);
                    aF[mf][2] = *(const uint32_t*)(p + 16);
                    aF[mf][3] = *(const uint32_t*)(p + 8 * RA_STR + 16);
                }
#pragma unroll
                for (int nf = 0; nf < 4; nf++) {
                    const char* p = sm + (nf * 8 + g) * RW_STR + (k0w + kk + tq * 2) * 2;   // FIX
                    bH[nf][0] = *(const uint32_t*)p;
                    bH[nf][1] = *(const uint32_t*)(p + 16);
                }
#pragma unroll
                for (int mf = 0; mf < 2; mf++)
#pragma unroll
                    for (int nf = 0; nf < 4; nf++)
                        mma16816(acc[mf][nf][0], acc[mf][nf][1], acc[mf][nf][2], acc[mf][nf][3],
                                 aF[mf][0], aF[mf][1], aF[mf][2], aF[mf][3],
                                 bH[nf][0], bH[nf][1]);
                if (two) {
#pragma unroll
                    for (int nf = 0; nf < 4; nf++) {
                        const char* p = sm + R_WSEG + (nf * 8 + g) * RW_STR + (k0w + kk + tq * 2) * 2;  // FIX
                        uint32_t b0 = *(const uint32_t*)p;
                        uint32_t b1 = *(const uint32_t*)(p + 16);
#pragma unroll
                        for (int mf = 0; mf < 2; mf++)
                            mma16816(acc[mf][nf][0], acc[mf][nf][1], acc[mf][nf][2], acc[mf][nf][3],
                                     aF[mf][0], aF[mf][1], aF[mf][2], aF[mf][3], b0, b1);
                    }
                }
            }
            __syncthreads();
        }

        {
            float* Gs = GsAll + kteam * 2048;
#pragma unroll
            for (int mf = 0; mf < 2; mf++) {
                int b = mw * 32 + mf * 16 + g;
#pragma unroll
                for (int nf = 0; nf < 4; nf++) {
                    int c = nf * 8 + tq * 2;
                    float2 v0 = { acc[mf][nf][0], acc[mf][nf][1] };
                    float2 v1 = { acc[mf][nf][2], acc[mf][nf][3] };
                    *(float2*)&Gs[b * 32 + c] = v0;
                    *(float2*)&Gs[(b + 8) * 32 + c] = v1;
                }
            }
        }
        __syncthreads();

        const float* hprevf = pr ? g_hB : g_hA;
        float* hnextf       = pr ? g_hA : g_hB;
        __nv_bfloat16* nhhi = g_h16hi[pr ^ 1];
        __nv_bfloat16* nhlo = g_h16lo[pr ^ 1];
        for (int it = tid; it < 512; it += 256) {
            int b = it >> 3, jl = it & 7;
            int j = j0 + jl;
            if (b < Bt) {
                int o0 = b * 32;
                float gi = GsAll[o0 + jl]      + GsAll[2048 + o0 + jl]      + GsAll[4096 + o0 + jl]      + GsAll[6144 + o0 + jl]      + sG[o0 + jl];
                float gf = GsAll[o0 + 8 + jl]  + GsAll[2048 + o0 + 8 + jl]  + GsAll[4096 + o0 + 8 + jl]  + GsAll[6144 + o0 + 8 + jl]  + sG[o0 + 8 + jl];
                float gg = GsAll[o0 + 16 + jl] + GsAll[2048 + o0 + 16 + jl] + GsAll[4096 + o0 + 16 + jl] + GsAll[6144 + o0 + 16 + jl] + sG[o0 + 16 + jl];
                float go = GsAll[o0 + 24 + jl] + GsAll[2048 + o0 + 24 + jl] + GsAll[4096 + o0 + 24 + jl] + GsAll[6144 + o0 + 24 + jl] + sG[o0 + 24 + jl];
                float i_ = 1.f / (1.f + __expf(-gi));
                float f_ = 1.f / (1.f + __expf(-gf));
                float g_ = tanhf(gg);
                float o_ = 1.f / (1.f + __expf(-go));
                float c_old = g_cS[b * HDIM + j];
                float c2 = f_ * c_old + i_ * g_;
                float h2 = o_ * tanhf(c2);
                g_cS[b * HDIM + j] = c2;
                hnextf[b * HDIM + j] = h2;
                __nv_bfloat16 hh = __float2bfloat16(h2);
                nhhi[b * HDIM + j] = hh;
                nhlo[b * HDIM + j] = __float2bfloat16(h2 - __bfloat162float(hh));
                out[(size_t)(off + b) * HDIM + j] = h2;
            } else {
                hnextf[b * HDIM + j] = hprevf[b * HDIM + j];
                nhhi[b * HDIM + j] = hhi[b * HDIM + j];
                nhlo[b * HDIM + j] = hlo[b * HDIM + j];
            }
        }

        __syncthreads();
        if (tid == 0) {
            __threadfence();
            atomicAdd(&g_bar, 1u);
            unsigned target = (unsigned)(t + 1) * (unsigned)NBLK;
            while (*(volatile unsigned*)&g_bar < target) { }
            __threadfence();
        }
        __syncthreads();
    }
}

// ---------------- final ----------------
__global__ void final_kernel(float* __restrict__ out, int total, int finalA) {
    const float* hf = finalA ? g_hA : g_hB;
    size_t base = (size_t)total * HDIM;
    int n = BMAX * HDIM;
    for (int i = blockIdx.x * blockDim.x + threadIdx.x; i < n; i += gridDim.x * blockDim.x) {
        out[base + i]     = hf[i];
        out[base + n + i] = g_cS[i];
    }
}

// ---------------- launch ----------------
extern "C" void kernel_launch(void* const* d_in, const int* in_sizes, int n_in,
                              void* d_out, int out_size) {
    const float* data = (const float*)d_in[0];
    const void*  bs   = d_in[1];
    const float* W_ih = (const float*)d_in[2];
    const float* W_hh = (const float*)d_in[3];
    const float* b_ih = (const float*)d_in[4];
    const float* b_hh = (const float*)d_in[5];
    const float* h0   = (const float*)d_in[6];
    const float* c0   = (const float*)d_in[7];
    float* out = (float*)d_out;

    int total = in_sizes[0] / D_IN;
    int T = in_sizes[1];
    if (T > TMAXQ) T = T / 2;
    if (T > TMAXQ) T = TMAXQ;

    cudaFuncSetAttribute(gemm_input_tc, cudaFuncAttributeMaxDynamicSharedMemorySize, GI_SMEM);
    cudaFuncSetAttribute(step_persistent, cudaFuncAttributeMaxDynamicSharedMemorySize, R_SMEM);

    prep_kernel<<<1, 256>>>(bs, h0, c0, T);

    __nv_bfloat16 *dhi, *dlo, *whi, *wlo;
    cudaGetSymbolAddress((void**)&dhi, g_data_hi);
    cudaGetSymbolAddress((void**)&dlo, g_data_lo);
    cudaGetSymbolAddress((void**)&whi, g_w_hi);
    cudaGetSymbolAddress((void**)&wlo, g_w_lo);
    split_kernel<<<4096, 256>>>(data, dhi, dlo, (size_t)total * D_IN);
    split_kernel<<<2048, 256>>>(W_ih, whi, wlo, (size_t)NGATE * D_IN);

    dim3 grid((total + 127) / 128, NGATE / 128);
    gemm_input_tc<<<grid, 256, GI_SMEM>>>(b_ih, b_hh, total);

    step_persistent<<<NBLK, 256, R_SMEM>>>(W_hh, out, T);

    long long need = (long long)total * HDIM + 2LL * BMAX * HDIM;
    if ((long long)out_size >= need)
        final_kernel<<<64, 256>>>(out, total, (T & 1) ? 0 : 1);
}

// round 6
// speedup vs baseline: 3.0387x; 1.1072x over previous
#include <cuda_runtime.h>
#include <cuda_bf16.h>
#include <math.h>
#include <stdint.h>

#define D_IN   1024
#define HDIM   1024
#define BMAX   64
#define TMAXQ  1000
#define NGATE  4096
#define TOTAL_MAX 47872
#define NBLK   128

// ---------------- device scratch ----------------
__device__ float g_gates[(size_t)TOTAL_MAX * NGATE];
__device__ __nv_bfloat16 g_data_hi[(size_t)TOTAL_MAX * D_IN];
__device__ __nv_bfloat16 g_data_lo[(size_t)TOTAL_MAX * D_IN];
__device__ __nv_bfloat16 g_w_hi[(size_t)NGATE * D_IN];
__device__ __nv_bfloat16 g_w_lo[(size_t)NGATE * D_IN];
__device__ __nv_bfloat16 g_h16hi[2][BMAX * HDIM];
__device__ __nv_bfloat16 g_h16lo[2][BMAX * HDIM];
__device__ float g_hA[BMAX * HDIM];
__device__ float g_hB[BMAX * HDIM];
__device__ float g_cS[BMAX * HDIM];
__device__ int   g_bs[TMAXQ];
__device__ int   g_off[TMAXQ + 1];
__device__ unsigned g_bar;

// ---------------- helpers ----------------
__device__ __forceinline__ uint32_t smem_u32(const void* p) {
    uint32_t a;
    asm("{ .reg .u64 t; cvta.to.shared.u64 t, %1; cvt.u32.u64 %0, t; }" : "=r"(a) : "l"(p));
    return a;
}
__device__ __forceinline__ void cp16(uint32_t dst, const void* src) {
    asm volatile("cp.async.cg.shared.global [%0], [%1], 16;" :: "r"(dst), "l"(src));
}
#define CP_COMMIT() asm volatile("cp.async.commit_group;" ::: "memory")
#define CP_WAIT2()  asm volatile("cp.async.wait_group 2;"  ::: "memory")
#define CP_WAIT1()  asm volatile("cp.async.wait_group 1;"  ::: "memory")
#define CP_WAIT0()  asm volatile("cp.async.wait_group 0;"  ::: "memory")

__device__ __forceinline__ void mma16816(float& d0, float& d1, float& d2, float& d3,
                                         uint32_t a0, uint32_t a1, uint32_t a2, uint32_t a3,
                                         uint32_t b0, uint32_t b1) {
    asm volatile(
        "mma.sync.aligned.m16n8k16.row.col.f32.bf16.bf16.f32 "
        "{%0,%1,%2,%3}, {%4,%5,%6,%7}, {%8,%9}, {%0,%1,%2,%3};"
        : "+f"(d0), "+f"(d1), "+f"(d2), "+f"(d3)
        : "r"(a0), "r"(a1), "r"(a2), "r"(a3), "r"(b0), "r"(b1));
}

__device__ __forceinline__ uint32_t pack_bf16(__nv_bfloat16 lo, __nv_bfloat16 hi) {
    return (uint32_t)__bfloat16_as_ushort(lo) | ((uint32_t)__bfloat16_as_ushort(hi) << 16);
}

// ---------------- prep ----------------
__global__ void prep_kernel(const void* __restrict__ bs_raw,
                            const float* __restrict__ h0,
                            const float* __restrict__ c0, int T) {
    __shared__ int sbs[TMAXQ];
    const int* p = (const int*)bs_raw;
    bool is64 = (p[1] == 0);
    int tid = threadIdx.x;
    for (int t = tid; t < T; t += blockDim.x) sbs[t] = is64 ? p[2 * t] : p[t];
    __syncthreads();
    if (tid == 0) {
        g_bar = 0u;
        int acc = 0;
        for (int t = 0; t < T; t++) { g_off[t] = acc; g_bs[t] = sbs[t]; acc += sbs[t]; }
        g_off[T] = acc;
    }
    for (int i = tid; i < BMAX * HDIM; i += blockDim.x) {
        float x = h0[i];
        g_hA[i] = x;
        g_cS[i] = c0[i];
        __nv_bfloat16 hh = __float2bfloat16(x);
        g_h16hi[0][i] = hh;
        g_h16lo[0][i] = __float2bfloat16(x - __bfloat162float(hh));
    }
}

// ---------------- fp32 -> bf16 hi/lo split ----------------
__global__ void split_kernel(const float* __restrict__ src,
                             __nv_bfloat16* __restrict__ hi,
                             __nv_bfloat16* __restrict__ lo, size_t n) {
    for (size_t i = (size_t)blockIdx.x * blockDim.x + threadIdx.x; i < n;
         i += (size_t)gridDim.x * blockDim.x) {
        float x = src[i];
        __nv_bfloat16 h = __float2bfloat16(x);
        hi[i] = h;
        lo[i] = __float2bfloat16(x - __bfloat162float(h));
    }
}

// ---------------- input GEMM via mma.sync bf16 split, 3-stage pipeline -------
// BM=128, BN=128, BK=32; keff = 3072 (A:[hi,hi,lo], B:[hi,lo,hi]); 8 warps.
#define GI_STR    80
#define GI_OFF_BIAS 0
#define GI_OFF_A  512
#define GI_STG    (128 * GI_STR)                 // 10240
#define GI_OFF_B  (GI_OFF_A + 3 * GI_STG)        // 31232
#define GI_SMEM   (GI_OFF_B + 3 * GI_STG)        // 61952

__global__ __launch_bounds__(256) void gemm_input_tc(
    const float* __restrict__ b_ih, const float* __restrict__ b_hh, int total) {
    extern __shared__ __align__(16) char sm[];
    float* sBias = (float*)(sm + GI_OFF_BIAS);
    uint32_t sb = smem_u32(sm);
    int tid = threadIdx.x, wid = tid >> 5, lane = tid & 31;
    int g = lane >> 2, tq = lane & 3;
    int row0 = blockIdx.x * 128, col0 = blockIdx.y * 128;
    int wm = wid & 1, wn = wid >> 1;

    for (int i = tid; i < 128; i += 256) sBias[i] = b_ih[col0 + i] + b_hh[col0 + i];

    float acc[4][4][4];
#pragma unroll
    for (int mf = 0; mf < 4; mf++)
#pragma unroll
        for (int nf = 0; nf < 4; nf++)
#pragma unroll
            for (int q = 0; q < 4; q++) acc[mf][nf][q] = 0.f;

    auto do_stage = [&](int st) {
        int buf = st % 3;
        int keff = st * 32;
        int s = keff >> 10, k0 = keff & 1023;
        const __nv_bfloat16* As = (s == 2) ? g_data_lo : g_data_hi;
        const __nv_bfloat16* Bs = (s == 1) ? g_w_lo : g_w_hi;
#pragma unroll
        for (int r = 0; r < 2; r++) {
            int c = tid + r * 256;
            int m = c >> 2, kc = (c & 3) * 8;
            int row = row0 + m; if (row >= total) row = total - 1;
            cp16(sb + GI_OFF_A + buf * GI_STG + m * GI_STR + kc * 2,
                 As + (size_t)row * 1024 + k0 + kc);
        }
#pragma unroll
        for (int r = 0; r < 2; r++) {
            int c = tid + r * 256;
            int m = c >> 2, kc = (c & 3) * 8;
            cp16(sb + GI_OFF_B + buf * GI_STG + m * GI_STR + kc * 2,
                 Bs + (size_t)(col0 + m) * 1024 + k0 + kc);
        }
        CP_COMMIT();
    };

    do_stage(0);
    do_stage(1);
    for (int st = 0; st < 96; ++st) {
        if (st + 2 < 96) do_stage(st + 2);
        int rem = 95 - st;
        if (rem >= 2) { CP_WAIT2(); } else if (rem == 1) { CP_WAIT1(); } else { CP_WAIT0(); }
        __syncthreads();
        int buf = st % 3;
        const char* pA = sm + GI_OFF_A + buf * GI_STG;
        const char* pB = sm + GI_OFF_B + buf * GI_STG;
#pragma unroll
        for (int kk = 0; kk < 32; kk += 16) {
            uint32_t aF[4][4], bF[4][2];
#pragma unroll
            for (int mf = 0; mf < 4; mf++) {
                const char* p = pA + (wm * 64 + mf * 16 + g) * GI_STR + (kk + tq * 2) * 2;
                aF[mf][0] = *(const uint32_t*)p;
                aF[mf][1] = *(const uint32_t*)(p + 8 * GI_STR);
                aF[mf][2] = *(const uint32_t*)(p + 16);
                aF[mf][3] = *(const uint32_t*)(p + 8 * GI_STR + 16);
            }
#pragma unroll
            for (int nf = 0; nf < 4; nf++) {
                const char* p = pB + (wn * 32 + nf * 8 + g) * GI_STR + (kk + tq * 2) * 2;
                bF[nf][0] = *(const uint32_t*)p;
                bF[nf][1] = *(const uint32_t*)(p + 16);
            }
#pragma unroll
            for (int mf = 0; mf < 4; mf++)
#pragma unroll
                for (int nf = 0; nf < 4; nf++)
                    mma16816(acc[mf][nf][0], acc[mf][nf][1], acc[mf][nf][2], acc[mf][nf][3],
                             aF[mf][0], aF[mf][1], aF[mf][2], aF[mf][3],
                             bF[nf][0], bF[nf][1]);
        }
        __syncthreads();
    }

#pragma unroll
    for (int mf = 0; mf < 4; mf++) {
        int r0 = row0 + wm * 64 + mf * 16 + g;
#pragma unroll
        for (int nf = 0; nf < 4; nf++) {
            int cl = wn * 32 + nf * 8 + tq * 2;
            float bb0 = sBias[cl], bb1 = sBias[cl + 1];
            if (r0 < total) {
                float2 v = { acc[mf][nf][0] + bb0, acc[mf][nf][1] + bb1 };
                *(float2*)&g_gates[(size_t)r0 * NGATE + col0 + cl] = v;
            }
            if (r0 + 8 < total) {
                float2 v = { acc[mf][nf][2] + bb0, acc[mf][nf][3] + bb1 };
                *(float2*)&g_gates[(size_t)(r0 + 8) * NGATE + col0 + cl] = v;
            }
        }
    }
}

// ---------------- persistent recurrence via mma.sync -------------------------
// 8 warps = 4 m-warps (16 rows each) x 2 k-teams (64 k per 128-k stage).
// 8 stages/step; each stage carries hi AND lo h for one 128-k range.
// Inactive m-warps (rows >= Bt) skip all MMA work.
#define RW_STR   2064
#define R_WSEG   (32 * RW_STR)                 // 66048
#define R_OFF_A  (2 * R_WSEG)                  // 132096
#define RA_STR   272
#define R_ASTG   (128 * RA_STR)                // 34816 (hi rows 0-63, lo rows 64-127)
#define R_OFF_GS (R_OFF_A + 2 * R_ASTG)        // 201728
#define R_OFF_SG (R_OFF_GS + 2 * 8192)         // 218112
#define R_SMEM   (R_OFF_SG + 8192)             // 226304

__global__ __launch_bounds__(256) void step_persistent(
    const float* __restrict__ W_hh, float* __restrict__ out, int T) {
    extern __shared__ __align__(16) char sm[];
    uint32_t sb = smem_u32(sm);
    float* GsAll = (float*)(sm + R_OFF_GS);
    float* sG = (float*)(sm + R_OFF_SG);
    int tid = threadIdx.x, wid = tid >> 5, lane = tid & 31;
    int g = lane >> 2, tq = lane & 3;
    int j0 = blockIdx.x * 8;
    int mw = wid & 3, kteam = wid >> 2;

    // one-time: convert this block's W_hh cols (fp32 -> bf16 hi/lo)
    for (int idx = tid; idx < 8192; idx += 256) {
        int c = idx >> 8;
        int k = (idx & 255) * 4;
        int n = (c >> 3) * HDIM + j0 + (c & 7);
        float4 v = *(const float4*)&W_hh[(size_t)n * HDIM + k];
        __nv_bfloat16 h0 = __float2bfloat16(v.x), h1 = __float2bfloat16(v.y);
        __nv_bfloat16 h2 = __float2bfloat16(v.z), h3 = __float2bfloat16(v.w);
        __nv_bfloat16 l0 = __float2bfloat16(v.x - __bfloat162float(h0));
        __nv_bfloat16 l1 = __float2bfloat16(v.y - __bfloat162float(h1));
        __nv_bfloat16 l2 = __float2bfloat16(v.z - __bfloat162float(h2));
        __nv_bfloat16 l3 = __float2bfloat16(v.w - __bfloat162float(h3));
        char* ph = sm + c * RW_STR + k * 2;
        char* pl = ph + R_WSEG;
        *(uint32_t*)ph = pack_bf16(h0, h1); *(uint32_t*)(ph + 4) = pack_bf16(h2, h3);
        *(uint32_t*)pl = pack_bf16(l0, l1); *(uint32_t*)(pl + 4) = pack_bf16(l2, l3);
    }
    __syncthreads();

    for (int t = 0; t < T; t++) {
        int pr = t & 1;
        const __nv_bfloat16* hhi = g_h16hi[pr];
        const __nv_bfloat16* hlo = g_h16lo[pr];
        int Bt = g_bs[t], off = g_off[t];
        int Btr = (Bt + 15) & ~15;

        auto stageA = [&](int st) {
            int buf = st & 1;
            int k0 = st * 128;
#pragma unroll
            for (int r = 0; r < 8; r++) {
                int c = tid + r * 256;            // 0..2047
                int seg = c >> 10;                // 0 hi, 1 lo
                int ci = c & 1023;
                int b = ci >> 4, kc = (ci & 15) * 8;
                if (b < Btr)
                    cp16(sb + R_OFF_A + buf * R_ASTG + (seg * 64 + b) * RA_STR + kc * 2,
                         (seg ? hlo : hhi) + b * 1024 + k0 + kc);
            }
        };

        {
#pragma unroll
            for (int u = 0; u < 2; u++) {
                int id = tid * 2 + u;
                int b = id >> 3, gi = (id >> 1) & 3, half = id & 1;
                int bc = (b < Bt) ? b : (Bt - 1);
                cp16(sb + R_OFF_SG + (uint32_t)(b * 32 + gi * 8 + half * 4) * 4,
                     &g_gates[(size_t)(off + bc) * NGATE + gi * HDIM + j0 + half * 4]);
            }
            stageA(0);
            CP_COMMIT();
        }

        bool wact = (mw * 16) < Bt;
        float acc[4][4];
#pragma unroll
        for (int nf = 0; nf < 4; nf++)
#pragma unroll
            for (int q = 0; q < 4; q++) acc[nf][q] = 0.f;

        for (int st = 0; st < 8; ++st) {
            if (st < 7) { stageA(st + 1); CP_COMMIT(); CP_WAIT1(); } else { CP_WAIT0(); }
            __syncthreads();
            if (wact) {
                int buf = st & 1;
                int k0w = st * 128;
                const char* pA = sm + R_OFF_A + buf * R_ASTG + (mw * 16 + g) * RA_STR;
#pragma unroll
                for (int u = 0; u < 4; u++) {
                    int kk = kteam * 64 + u * 16;
                    const char* pa = pA + (kk + tq * 2) * 2;
                    uint32_t aH[4], aL[4];
                    aH[0] = *(const uint32_t*)pa;
                    aH[1] = *(const uint32_t*)(pa + 8 * RA_STR);
                    aH[2] = *(const uint32_t*)(pa + 16);
                    aH[3] = *(const uint32_t*)(pa + 8 * RA_STR + 16);
                    const char* pal = pa + 64 * RA_STR;
                    aL[0] = *(const uint32_t*)pal;
                    aL[1] = *(const uint32_t*)(pal + 8 * RA_STR);
                    aL[2] = *(const uint32_t*)(pal + 16);
                    aL[3] = *(const uint32_t*)(pal + 8 * RA_STR + 16);
#pragma unroll
                    for (int nf = 0; nf < 4; nf++) {
                        const char* pbh = sm + (nf * 8 + g) * RW_STR + (k0w + kk + tq * 2) * 2;
                        uint32_t bh0 = *(const uint32_t*)pbh;
                        uint32_t bh1 = *(const uint32_t*)(pbh + 16);
                        const char* pbl = pbh + R_WSEG;
                        uint32_t bl0 = *(const uint32_t*)pbl;
                        uint32_t bl1 = *(const uint32_t*)(pbl + 16);
                        mma16816(acc[nf][0], acc[nf][1], acc[nf][2], acc[nf][3],
                                 aH[0], aH[1], aH[2], aH[3], bh0, bh1);
                        mma16816(acc[nf][0], acc[nf][1], acc[nf][2], acc[nf][3],
                                 aH[0], aH[1], aH[2], aH[3], bl0, bl1);
                        mma16816(acc[nf][0], acc[nf][1], acc[nf][2], acc[nf][3],
                                 aL[0], aL[1], aL[2], aL[3], bh0, bh1);
                    }
                }
            }
            __syncthreads();
        }

        if (wact) {
            float* Gs = GsAll + kteam * 2048;
            int b = mw * 16 + g;
#pragma unroll
            for (int nf = 0; nf < 4; nf++) {
                int c = nf * 8 + tq * 2;
                float2 v0 = { acc[nf][0], acc[nf][1] };
                float2 v1 = { acc[nf][2], acc[nf][3] };
                *(float2*)&Gs[b * 32 + c] = v0;
                *(float2*)&Gs[(b + 8) * 32 + c] = v1;
            }
        }
        __syncthreads();

        const float* hprevf = pr ? g_hB : g_hA;
        float* hnextf       = pr ? g_hA : g_hB;
        __nv_bfloat16* nhhi = g_h16hi[pr ^ 1];
        __nv_bfloat16* nhlo = g_h16lo[pr ^ 1];
        for (int it = tid; it < 512; it += 256) {
            int b = it >> 3, jl = it & 7;
            int j = j0 + jl;
            if (b < Bt) {
                int o0 = b * 32;
                float gi = GsAll[o0 + jl]      + GsAll[2048 + o0 + jl]      + sG[o0 + jl];
                float gf = GsAll[o0 + 8 + jl]  + GsAll[2048 + o0 + 8 + jl]  + sG[o0 + 8 + jl];
                float gg = GsAll[o0 + 16 + jl] + GsAll[2048 + o0 + 16 + jl] + sG[o0 + 16 + jl];
                float go = GsAll[o0 + 24 + jl] + GsAll[2048 + o0 + 24 + jl] + sG[o0 + 24 + jl];
                float i_ = 1.f / (1.f + __expf(-gi));
                float f_ = 1.f / (1.f + __expf(-gf));
                float g_ = tanhf(gg);
                float o_ = 1.f / (1.f + __expf(-go));
                float c_old = g_cS[b * HDIM + j];
                float c2 = f_ * c_old + i_ * g_;
                float h2 = o_ * tanhf(c2);
                g_cS[b * HDIM + j] = c2;
                hnextf[b * HDIM + j] = h2;
                __nv_bfloat16 hh = __float2bfloat16(h2);
                nhhi[b * HDIM + j] = hh;
                nhlo[b * HDIM + j] = __float2bfloat16(h2 - __bfloat162float(hh));
                out[(size_t)(off + b) * HDIM + j] = h2;
            } else {
                hnextf[b * HDIM + j] = hprevf[b * HDIM + j];
                nhhi[b * HDIM + j] = hhi[b * HDIM + j];
                nhlo[b * HDIM + j] = hlo[b * HDIM + j];
            }
        }

        __syncthreads();
        if (tid == 0) {
            __threadfence();
            atomicAdd(&g_bar, 1u);
            unsigned target = (unsigned)(t + 1) * (unsigned)NBLK;
            while (*(volatile unsigned*)&g_bar < target) { }
            __threadfence();
        }
        __syncthreads();
    }
}

// ---------------- final ----------------
__global__ void final_kernel(float* __restrict__ out, int total, int finalA) {
    const float* hf = finalA ? g_hA : g_hB;
    size_t base = (size_t)total * HDIM;
    int n = BMAX * HDIM;
    for (int i = blockIdx.x * blockDim.x + threadIdx.x; i < n; i += gridDim.x * blockDim.x) {
        out[base + i]     = hf[i];
        out[base + n + i] = g_cS[i];
    }
}

// ---------------- launch ----------------
extern "C" void kernel_launch(void* const* d_in, const int* in_sizes, int n_in,
                              void* d_out, int out_size) {
    const float* data = (const float*)d_in[0];
    const void*  bs   = d_in[1];
    const float* W_ih = (const float*)d_in[2];
    const float* W_hh = (const float*)d_in[3];
    const float* b_ih = (const float*)d_in[4];
    const float* b_hh = (const float*)d_in[5];
    const float* h0   = (const float*)d_in[6];
    const float* c0   = (const float*)d_in[7];
    float* out = (float*)d_out;

    int total = in_sizes[0] / D_IN;
    int T = in_sizes[1];
    if (T > TMAXQ) T = T / 2;
    if (T > TMAXQ) T = TMAXQ;

    cudaFuncSetAttribute(gemm_input_tc, cudaFuncAttributeMaxDynamicSharedMemorySize, GI_SMEM);
    cudaFuncSetAttribute(step_persistent, cudaFuncAttributeMaxDynamicSharedMemorySize, R_SMEM);

    prep_kernel<<<1, 256>>>(bs, h0, c0, T);

    __nv_bfloat16 *dhi, *dlo, *whi, *wlo;
    cudaGetSymbolAddress((void**)&dhi, g_data_hi);
    cudaGetSymbolAddress((void**)&dlo, g_data_lo);
    cudaGetSymbolAddress((void**)&whi, g_w_hi);
    cudaGetSymbolAddress((void**)&wlo, g_w_lo);
    split_kernel<<<4096, 256>>>(data, dhi, dlo, (size_t)total * D_IN);
    split_kernel<<<2048, 256>>>(W_ih, whi, wlo, (size_t)NGATE * D_IN);

    dim3 grid((total + 127) / 128, NGATE / 128);
    gemm_input_tc<<<grid, 256, GI_SMEM>>>(b_ih, b_hh, total);

    step_persistent<<<NBLK, 256, R_SMEM>>>(W_hh, out, T);

    long long need = (long long)total * HDIM + 2LL * BMAX * HDIM;
    if ((long long)out_size >= need)
        final_kernel<<<64, 256>>>(out, total, (T & 1) ? 0 : 1);
}

// round 7
// speedup vs baseline: 3.5525x; 1.1691x over previous
#include <cuda_runtime.h>
#include <cuda_bf16.h>
#include <math.h>
#include <stdint.h>

#define D_IN   1024
#define HDIM   1024
#define BMAX   64
#define TMAXQ  1000
#define NGATE  4096
#define TOTAL_MAX 47872
#define NBLK   128

// ---------------- device scratch ----------------
__device__ float g_gates[(size_t)TOTAL_MAX * NGATE];
__device__ __nv_bfloat16 g_data_hi[(size_t)TOTAL_MAX * D_IN];
__device__ __nv_bfloat16 g_data_lo[(size_t)TOTAL_MAX * D_IN];
__device__ __nv_bfloat16 g_w_hi[(size_t)NGATE * D_IN];
__device__ __nv_bfloat16 g_w_lo[(size_t)NGATE * D_IN];
__device__ __nv_bfloat16 g_h16hi[2][BMAX * HDIM];
__device__ __nv_bfloat16 g_h16lo[2][BMAX * HDIM];
__device__ float g_hA[BMAX * HDIM];
__device__ float g_hB[BMAX * HDIM];
__device__ float g_cS[BMAX * HDIM];
__device__ int   g_bs[TMAXQ];
__device__ int   g_off[TMAXQ + 1];
__device__ unsigned g_bar;

// ---------------- helpers ----------------
__device__ __forceinline__ uint32_t smem_u32(const void* p) {
    uint32_t a;
    asm("{ .reg .u64 t; cvta.to.shared.u64 t, %1; cvt.u32.u64 %0, t; }" : "=r"(a) : "l"(p));
    return a;
}
__device__ __forceinline__ void cp16(uint32_t dst, const void* src) {
    asm volatile("cp.async.cg.shared.global [%0], [%1], 16;" :: "r"(dst), "l"(src));
}
#define CP_COMMIT() asm volatile("cp.async.commit_group;" ::: "memory")
#define CP_WAIT2()  asm volatile("cp.async.wait_group 2;"  ::: "memory")
#define CP_WAIT1()  asm volatile("cp.async.wait_group 1;"  ::: "memory")
#define CP_WAIT0()  asm volatile("cp.async.wait_group 0;"  ::: "memory")

__device__ __forceinline__ void mma16816(float& d0, float& d1, float& d2, float& d3,
                                         uint32_t a0, uint32_t a1, uint32_t a2, uint32_t a3,
                                         uint32_t b0, uint32_t b1) {
    asm volatile(
        "mma.sync.aligned.m16n8k16.row.col.f32.bf16.bf16.f32 "
        "{%0,%1,%2,%3}, {%4,%5,%6,%7}, {%8,%9}, {%0,%1,%2,%3};"
        : "+f"(d0), "+f"(d1), "+f"(d2), "+f"(d3)
        : "r"(a0), "r"(a1), "r"(a2), "r"(a3), "r"(b0), "r"(b1));
}
__device__ __forceinline__ void ldsm4(uint32_t& r0, uint32_t& r1, uint32_t& r2, uint32_t& r3,
                                      uint32_t addr) {
    asm volatile("ldmatrix.sync.aligned.m8n8.x4.shared.b16 {%0,%1,%2,%3}, [%4];"
                 : "=r"(r0), "=r"(r1), "=r"(r2), "=r"(r3) : "r"(addr));
}
__device__ __forceinline__ uint32_t pack_bf16(__nv_bfloat16 lo, __nv_bfloat16 hi) {
    return (uint32_t)__bfloat16_as_ushort(lo) | ((uint32_t)__bfloat16_as_ushort(hi) << 16);
}

// ---------------- prep ----------------
__global__ void prep_kernel(const void* __restrict__ bs_raw,
                            const float* __restrict__ h0,
                            const float* __restrict__ c0, int T) {
    __shared__ int sbs[TMAXQ];
    const int* p = (const int*)bs_raw;
    bool is64 = (p[1] == 0);
    int tid = threadIdx.x;
    for (int t = tid; t < T; t += blockDim.x) sbs[t] = is64 ? p[2 * t] : p[t];
    __syncthreads();
    if (tid == 0) {
        g_bar = 0u;
        int acc = 0;
        for (int t = 0; t < T; t++) { g_off[t] = acc; g_bs[t] = sbs[t]; acc += sbs[t]; }
        g_off[T] = acc;
    }
    for (int i = tid; i < BMAX * HDIM; i += blockDim.x) {
        float x = h0[i];
        g_hA[i] = x;
        g_cS[i] = c0[i];
        __nv_bfloat16 hh = __float2bfloat16(x);
        g_h16hi[0][i] = hh;
        g_h16lo[0][i] = __float2bfloat16(x - __bfloat162float(hh));
    }
}

// ---------------- fp32 -> bf16 hi/lo split ----------------
__global__ void split_kernel(const float* __restrict__ src,
                             __nv_bfloat16* __restrict__ hi,
                             __nv_bfloat16* __restrict__ lo, size_t n) {
    for (size_t i = (size_t)blockIdx.x * blockDim.x + threadIdx.x; i < n;
         i += (size_t)gridDim.x * blockDim.x) {
        float x = src[i];
        __nv_bfloat16 h = __float2bfloat16(x);
        hi[i] = h;
        lo[i] = __float2bfloat16(x - __bfloat162float(h));
    }
}

// ---------------- input GEMM: mma.sync bf16 split, BK=64, ldmatrix -----------
// BM=128, BN=128, BK=64; 48 stages (keff=3072); 3-buffer cp.async pipeline.
// Grid: x = col blocks (fast) so concurrent col-blocks reuse A tiles via L2.
#define GI_STR    144                            // 64 bf16 + 16B pad
#define GI_OFF_BIAS 0
#define GI_OFF_A  512
#define GI_STG    (128 * GI_STR)                 // 18432
#define GI_OFF_B  (GI_OFF_A + 3 * GI_STG)        // 55808
#define GI_SMEM   (GI_OFF_B + 3 * GI_STG)        // 111104

__global__ __launch_bounds__(256) void gemm_input_tc(
    const float* __restrict__ b_ih, const float* __restrict__ b_hh, int total) {
    extern __shared__ __align__(16) char sm[];
    float* sBias = (float*)(sm + GI_OFF_BIAS);
    uint32_t sb = smem_u32(sm);
    int tid = threadIdx.x, wid = tid >> 5, lane = tid & 31;
    int tq = lane & 3;
    int col0 = blockIdx.x * 128, row0 = blockIdx.y * 128;
    int wm = wid & 1, wn = wid >> 1;

    int qr = lane & 7, qq = lane >> 3;
    int a_row = qr + ((qq & 1) << 3), a_k = (qq >> 1) << 3;   // A-type ldsm offsets
    int b_row = qr + ((qq >> 1) << 3), b_k = (qq & 1) << 3;   // B-type ldsm offsets

    for (int i = tid; i < 128; i += 256) sBias[i] = b_ih[col0 + i] + b_hh[col0 + i];

    float acc[4][4][4];
#pragma unroll
    for (int mf = 0; mf < 4; mf++)
#pragma unroll
        for (int nf = 0; nf < 4; nf++)
#pragma unroll
            for (int q = 0; q < 4; q++) acc[mf][nf][q] = 0.f;

    auto do_stage = [&](int st) {
        int buf = st % 3;
        int keff = st * 64;
        int s = keff >> 10, k0 = keff & 1023;
        const __nv_bfloat16* As = (s == 2) ? g_data_lo : g_data_hi;
        const __nv_bfloat16* Bs = (s == 1) ? g_w_lo : g_w_hi;
#pragma unroll
        for (int r = 0; r < 4; r++) {
            int c = tid + r * 256;                // 0..1023
            int m = c >> 3, kc = (c & 7) * 8;
            int row = row0 + m; if (row >= total) row = total - 1;
            cp16(sb + GI_OFF_A + buf * GI_STG + m * GI_STR + kc * 2,
                 As + (size_t)row * 1024 + k0 + kc);
        }
#pragma unroll
        for (int r = 0; r < 4; r++) {
            int c = tid + r * 256;
            int m = c >> 3, kc = (c & 7) * 8;
            cp16(sb + GI_OFF_B + buf * GI_STG + m * GI_STR + kc * 2,
                 Bs + (size_t)(col0 + m) * 1024 + k0 + kc);
        }
        CP_COMMIT();
    };

    do_stage(0);
    do_stage(1);
    for (int st = 0; st < 48; ++st) {
        if (st + 2 < 48) do_stage(st + 2);
        int rem = 47 - st;
        if (rem >= 2) { CP_WAIT2(); } else if (rem == 1) { CP_WAIT1(); } else { CP_WAIT0(); }
        __syncthreads();
        int buf = st % 3;
        uint32_t pA = sb + GI_OFF_A + buf * GI_STG;
        uint32_t pB = sb + GI_OFF_B + buf * GI_STG;
#pragma unroll
        for (int kk = 0; kk < 64; kk += 16) {
            uint32_t aF[4][4], bF[4][2];
#pragma unroll
            for (int mf = 0; mf < 4; mf++)
                ldsm4(aF[mf][0], aF[mf][1], aF[mf][2], aF[mf][3],
                      pA + (wm * 64 + mf * 16 + a_row) * GI_STR + (kk + a_k) * 2);
#pragma unroll
            for (int h = 0; h < 2; h++) {
                uint32_t r0, r1, r2, r3;
                ldsm4(r0, r1, r2, r3,
                      pB + (wn * 32 + h * 16 + b_row) * GI_STR + (kk + b_k) * 2);
                bF[h * 2][0] = r0; bF[h * 2][1] = r1;
                bF[h * 2 + 1][0] = r2; bF[h * 2 + 1][1] = r3;
            }
#pragma unroll
            for (int mf = 0; mf < 4; mf++)
#pragma unroll
                for (int nf = 0; nf < 4; nf++)
                    mma16816(acc[mf][nf][0], acc[mf][nf][1], acc[mf][nf][2], acc[mf][nf][3],
                             aF[mf][0], aF[mf][1], aF[mf][2], aF[mf][3],
                             bF[nf][0], bF[nf][1]);
        }
        __syncthreads();
    }

    int g = lane >> 2;
#pragma unroll
    for (int mf = 0; mf < 4; mf++) {
        int r0 = row0 + wm * 64 + mf * 16 + g;
#pragma unroll
        for (int nf = 0; nf < 4; nf++) {
            int cl = wn * 32 + nf * 8 + tq * 2;
            float bb0 = sBias[cl], bb1 = sBias[cl + 1];
            if (r0 < total) {
                float2 v = { acc[mf][nf][0] + bb0, acc[mf][nf][1] + bb1 };
                *(float2*)&g_gates[(size_t)r0 * NGATE + col0 + cl] = v;
            }
            if (r0 + 8 < total) {
                float2 v = { acc[mf][nf][2] + bb0, acc[mf][nf][3] + bb1 };
                *(float2*)&g_gates[(size_t)(r0 + 8) * NGATE + col0 + cl] = v;
            }
        }
    }
}

// ---------------- persistent recurrence via mma.sync + ldmatrix --------------
#define RW_STR   2064
#define R_WSEG   (32 * RW_STR)
#define R_OFF_A  (2 * R_WSEG)
#define RA_STR   272
#define R_ASTG   (128 * RA_STR)
#define R_OFF_GS (R_OFF_A + 2 * R_ASTG)
#define R_OFF_SG (R_OFF_GS + 2 * 8192)
#define R_SMEM   (R_OFF_SG + 8192)

__global__ __launch_bounds__(256) void step_persistent(
    const float* __restrict__ W_hh, float* __restrict__ out, int T) {
    extern __shared__ __align__(16) char sm[];
    uint32_t sb = smem_u32(sm);
    float* GsAll = (float*)(sm + R_OFF_GS);
    float* sG = (float*)(sm + R_OFF_SG);
    int tid = threadIdx.x, wid = tid >> 5, lane = tid & 31;
    int g = lane >> 2, tq = lane & 3;
    int j0 = blockIdx.x * 8;
    int mw = wid & 3, kteam = wid >> 2;

    int qr = lane & 7, qq = lane >> 3;
    int a_row = qr + ((qq & 1) << 3), a_k = (qq >> 1) << 3;
    int b_row = qr + ((qq >> 1) << 3), b_k = (qq & 1) << 3;

    // one-time: convert this block's W_hh cols (fp32 -> bf16 hi/lo)
    for (int idx = tid; idx < 8192; idx += 256) {
        int c = idx >> 8;
        int k = (idx & 255) * 4;
        int n = (c >> 3) * HDIM + j0 + (c & 7);
        float4 v = *(const float4*)&W_hh[(size_t)n * HDIM + k];
        __nv_bfloat16 h0 = __float2bfloat16(v.x), h1 = __float2bfloat16(v.y);
        __nv_bfloat16 h2 = __float2bfloat16(v.z), h3 = __float2bfloat16(v.w);
        __nv_bfloat16 l0 = __float2bfloat16(v.x - __bfloat162float(h0));
        __nv_bfloat16 l1 = __float2bfloat16(v.y - __bfloat162float(h1));
        __nv_bfloat16 l2 = __float2bfloat16(v.z - __bfloat162float(h2));
        __nv_bfloat16 l3 = __float2bfloat16(v.w - __bfloat162float(h3));
        char* ph = sm + c * RW_STR + k * 2;
        char* pl = ph + R_WSEG;
        *(uint32_t*)ph = pack_bf16(h0, h1); *(uint32_t*)(ph + 4) = pack_bf16(h2, h3);
        *(uint32_t*)pl = pack_bf16(l0, l1); *(uint32_t*)(pl + 4) = pack_bf16(l2, l3);
    }
    __syncthreads();

    for (int t = 0; t < T; t++) {
        int pr = t & 1;
        const __nv_bfloat16* hhi = g_h16hi[pr];
        const __nv_bfloat16* hlo = g_h16lo[pr];
        int Bt = g_bs[t], off = g_off[t];
        int Btr = (Bt + 15) & ~15;

        auto stageA = [&](int st) {
            int buf = st & 1;
            int k0 = st * 128;
#pragma unroll
            for (int r = 0; r < 8; r++) {
                int c = tid + r * 256;
                int seg = c >> 10;
                int ci = c & 1023;
                int b = ci >> 4, kc = (ci & 15) * 8;
                if (b < Btr)
                    cp16(sb + R_OFF_A + buf * R_ASTG + (seg * 64 + b) * RA_STR + kc * 2,
                         (seg ? hlo : hhi) + b * 1024 + k0 + kc);
            }
        };

        {
#pragma unroll
            for (int u = 0; u < 2; u++) {
                int id = tid * 2 + u;
                int b = id >> 3, gi = (id >> 1) & 3, half = id & 1;
                int bc = (b < Bt) ? b : (Bt - 1);
                cp16(sb + R_OFF_SG + (uint32_t)(b * 32 + gi * 8 + half * 4) * 4,
                     &g_gates[(size_t)(off + bc) * NGATE + gi * HDIM + j0 + half * 4]);
            }
            stageA(0);
            CP_COMMIT();
        }

        bool wact = (mw * 16) < Bt;
        float acc[4][4];
#pragma unroll
        for (int nf = 0; nf < 4; nf++)
#pragma unroll
            for (int q = 0; q < 4; q++) acc[nf][q] = 0.f;

        for (int st = 0; st < 8; ++st) {
            if (st < 7) { stageA(st + 1); CP_COMMIT(); CP_WAIT1(); } else { CP_WAIT0(); }
            __syncthreads();
            if (wact) {
                int buf = st & 1;
                int k0w = st * 128;
                uint32_t pA = sb + R_OFF_A + buf * R_ASTG + (mw * 16 + a_row) * RA_STR;
#pragma unroll
                for (int u = 0; u < 4; u++) {
                    int kk = kteam * 64 + u * 16;
                    uint32_t aH[4], aL[4];
                    ldsm4(aH[0], aH[1], aH[2], aH[3], pA + (kk + a_k) * 2);
                    ldsm4(aL[0], aL[1], aL[2], aL[3], pA + 64 * RA_STR + (kk + a_k) * 2);
                    uint32_t bh[4][2], bl[4][2];
#pragma unroll
                    for (int h = 0; h < 2; h++) {
                        uint32_t r0, r1, r2, r3;
                        uint32_t ab = sb + (h * 16 + b_row) * RW_STR + (k0w + kk + b_k) * 2;
                        ldsm4(r0, r1, r2, r3, ab);
                        bh[h * 2][0] = r0; bh[h * 2][1] = r1;
                        bh[h * 2 + 1][0] = r2; bh[h * 2 + 1][1] = r3;
                        ldsm4(r0, r1, r2, r3, ab + R_WSEG);
                        bl[h * 2][0] = r0; bl[h * 2][1] = r1;
                        bl[h * 2 + 1][0] = r2; bl[h * 2 + 1][1] = r3;
                    }
#pragma unroll
                    for (int nf = 0; nf < 4; nf++) {
                        mma16816(acc[nf][0], acc[nf][1], acc[nf][2], acc[nf][3],
                                 aH[0], aH[1], aH[2], aH[3], bh[nf][0], bh[nf][1]);
                        mma16816(acc[nf][0], acc[nf][1], acc[nf][2], acc[nf][3],
                                 aH[0], aH[1], aH[2], aH[3], bl[nf][0], bl[nf][1]);
                        mma16816(acc[nf][0], acc[nf][1], acc[nf][2], acc[nf][3],
                                 aL[0], aL[1], aL[2], aL[3], bh[nf][0], bh[nf][1]);
                    }
                }
            }
            __syncthreads();
        }

        if (wact) {
            float* Gs = GsAll + kteam * 2048;
            int b = mw * 16 + g;
#pragma unroll
            for (int nf = 0; nf < 4; nf++) {
                int c = nf * 8 + tq * 2;
                float2 v0 = { acc[nf][0], acc[nf][1] };
                float2 v1 = { acc[nf][2], acc[nf][3] };
                *(float2*)&Gs[b * 32 + c] = v0;
                *(float2*)&Gs[(b + 8) * 32 + c] = v1;
            }
        }
        __syncthreads();

        const float* hprevf = pr ? g_hB : g_hA;
        float* hnextf       = pr ? g_hA : g_hB;
        __nv_bfloat16* nhhi = g_h16hi[pr ^ 1];
        __nv_bfloat16* nhlo = g_h16lo[pr ^ 1];
        for (int it = tid; it < 512; it += 256) {
            int b = it >> 3, jl = it & 7;
            int j = j0 + jl;
            if (b < Bt) {
                int o0 = b * 32;
                float gi = GsAll[o0 + jl]      + GsAll[2048 + o0 + jl]      + sG[o0 + jl];
                float gf = GsAll[o0 + 8 + jl]  + GsAll[2048 + o0 + 8 + jl]  + sG[o0 + 8 + jl];
                float gg = GsAll[o0 + 16 + jl] + GsAll[2048 + o0 + 16 + jl] + sG[o0 + 16 + jl];
                float go = GsAll[o0 + 24 + jl] + GsAll[2048 + o0 + 24 + jl] + sG[o0 + 24 + jl];
                float i_ = 1.f / (1.f + __expf(-gi));
                float f_ = 1.f / (1.f + __expf(-gf));
                float g_ = tanhf(gg);
                float o_ = 1.f / (1.f + __expf(-go));
                float c_old = g_cS[b * HDIM + j];
                float c2 = f_ * c_old + i_ * g_;
                float h2 = o_ * tanhf(c2);
                g_cS[b * HDIM + j] = c2;
                hnextf[b * HDIM + j] = h2;
                __nv_bfloat16 hh = __float2bfloat16(h2);
                nhhi[b * HDIM + j] = hh;
                nhlo[b * HDIM + j] = __float2bfloat16(h2 - __bfloat162float(hh));
                out[(size_t)(off + b) * HDIM + j] = h2;
            } else {
                hnextf[b * HDIM + j] = hprevf[b * HDIM + j];
                nhhi[b * HDIM + j] = hhi[b * HDIM + j];
                nhlo[b * HDIM + j] = hlo[b * HDIM + j];
            }
        }

        // grid barrier: release-add + acquire-poll (cooperative-groups pattern)
        __syncthreads();
        if (tid == 0) {
            asm volatile("red.release.gpu.add.u32 [%0], %1;" :: "l"(&g_bar), "r"(1u) : "memory");
            unsigned target = (unsigned)(t + 1) * (unsigned)NBLK;
            unsigned v;
            do {
                asm volatile("ld.acquire.gpu.u32 %0, [%1];" : "=r"(v) : "l"(&g_bar) : "memory");
            } while (v < target);
        }
        __syncthreads();
    }
}

// ---------------- final ----------------
__global__ void final_kernel(float* __restrict__ out, int total, int finalA) {
    const float* hf = finalA ? g_hA : g_hB;
    size_t base = (size_t)total * HDIM;
    int n = BMAX * HDIM;
    for (int i = blockIdx.x * blockDim.x + threadIdx.x; i < n; i += gridDim.x * blockDim.x) {
        out[base + i]     = hf[i];
        out[base + n + i] = g_cS[i];
    }
}

// ---------------- launch ----------------
extern "C" void kernel_launch(void* const* d_in, const int* in_sizes, int n_in,
                              void* d_out, int out_size) {
    const float* data = (const float*)d_in[0];
    const void*  bs   = d_in[1];
    const float* W_ih = (const float*)d_in[2];
    const float* W_hh = (const float*)d_in[3];
    const float* b_ih = (const float*)d_in[4];
    const float* b_hh = (const float*)d_in[5];
    const float* h0   = (const float*)d_in[6];
    const float* c0   = (const float*)d_in[7];
    float* out = (float*)d_out;

    int total = in_sizes[0] / D_IN;
    int T = in_sizes[1];
    if (T > TMAXQ) T = T / 2;
    if (T > TMAXQ) T = TMAXQ;

    cudaFuncSetAttribute(gemm_input_tc, cudaFuncAttributeMaxDynamicSharedMemorySize, GI_SMEM);
    cudaFuncSetAttribute(step_persistent, cudaFuncAttributeMaxDynamicSharedMemorySize, R_SMEM);

    prep_kernel<<<1, 256>>>(bs, h0, c0, T);

    __nv_bfloat16 *dhi, *dlo, *whi, *wlo;
    cudaGetSymbolAddress((void**)&dhi, g_data_hi);
    cudaGetSymbolAddress((void**)&dlo, g_data_lo);
    cudaGetSymbolAddress((void**)&whi, g_w_hi);
    cudaGetSymbolAddress((void**)&wlo, g_w_lo);
    split_kernel<<<4096, 256>>>(data, dhi, dlo, (size_t)total * D_IN);
    split_kernel<<<2048, 256>>>(W_ih, whi, wlo, (size_t)NGATE * D_IN);

    // cols on x (fast) so a wave of col-blocks reuses each A tile via L2
    dim3 grid(NGATE / 128, (total + 127) / 128);
    gemm_input_tc<<<grid, 256, GI_SMEM>>>(b_ih, b_hh, total);

    step_persistent<<<NBLK, 256, R_SMEM>>>(W_hh, out, T);

    long long need = (long long)total * HDIM + 2LL * BMAX * HDIM;
    if ((long long)out_size >= need)
        final_kernel<<<64, 256>>>(out, total, (T & 1) ? 0 : 1);
}